// round 1
// baseline (speedup 1.0000x reference)
#include <cuda_runtime.h>

#define BB   8
#define TT   2048
#define CIN  1024
#define HD   128
#define BT   (BB*TT)          // 16384 rows

// Scratch for projected Q, K, V (static __device__ arrays: allocation-guard safe)
__device__ float g_q[BT * HD];
__device__ float g_k[BT * HD];
__device__ float g_v[BT * HD];

// ---------------------------------------------------------------------------
// Kernel 1: QKV projection GEMM.  Out[16384,128] = X[16384,1024] @ W[1024,128]
// blockIdx.y selects q/k/v. BM=64, BN=128, BK=16, 256 threads, 8x4 micro-tile.
// ---------------------------------------------------------------------------
__global__ __launch_bounds__(256) void qkv_gemm(
    const float* __restrict__ X,
    const float* __restrict__ Wq,
    const float* __restrict__ Wk,
    const float* __restrict__ Wv)
{
    const float* W  = (blockIdx.y == 0) ? Wq : (blockIdx.y == 1 ? Wk : Wv);
    float*       Out = (blockIdx.y == 0) ? g_q : (blockIdx.y == 1 ? g_k : g_v);

    __shared__ float Xs[64][20];    // padded to dodge store conflicts
    __shared__ float Ws[16][128];

    const int t  = threadIdx.x;
    const int m0 = blockIdx.x * 64;
    const int tm = t >> 5;          // 0..7  -> row group of 8
    const int tn = t & 31;          // 0..31 -> col group of 4

    float acc[8][4];
    #pragma unroll
    for (int r = 0; r < 8; r++)
        #pragma unroll
        for (int c = 0; c < 4; c++) acc[r][c] = 0.f;

    for (int k0 = 0; k0 < CIN; k0 += 16) {
        // load X tile 64x16 (one float4 per thread)
        {
            const int r = t >> 2;
            const int c = (t & 3) << 2;
            float4 v = *reinterpret_cast<const float4*>(X + (size_t)(m0 + r) * CIN + k0 + c);
            Xs[r][c + 0] = v.x; Xs[r][c + 1] = v.y;
            Xs[r][c + 2] = v.z; Xs[r][c + 3] = v.w;
        }
        // load W tile 16x128 (two float4 per thread)
        #pragma unroll
        for (int i = 0; i < 2; i++) {
            const int idx = t + i * 256;        // f4 index 0..511
            const int r = idx >> 5;
            const int c = (idx & 31) << 2;
            float4 v = *reinterpret_cast<const float4*>(W + (size_t)(k0 + r) * HD + c);
            *reinterpret_cast<float4*>(&Ws[r][c]) = v;
        }
        __syncthreads();

        #pragma unroll
        for (int kk = 0; kk < 16; kk++) {
            float4 bv = *reinterpret_cast<const float4*>(&Ws[kk][tn << 2]);
            #pragma unroll
            for (int r = 0; r < 8; r++) {
                float a = Xs[(tm << 3) + r][kk];
                acc[r][0] = fmaf(a, bv.x, acc[r][0]);
                acc[r][1] = fmaf(a, bv.y, acc[r][1]);
                acc[r][2] = fmaf(a, bv.z, acc[r][2]);
                acc[r][3] = fmaf(a, bv.w, acc[r][3]);
            }
        }
        __syncthreads();
    }

    #pragma unroll
    for (int r = 0; r < 8; r++) {
        float4 v = make_float4(acc[r][0], acc[r][1], acc[r][2], acc[r][3]);
        *reinterpret_cast<float4*>(Out + (size_t)(m0 + (tm << 3) + r) * HD + (tn << 2)) = v;
    }
}

// ---------------------------------------------------------------------------
// Kernel 2: causal flash attention, fp32.
// One block = one (batch, 64-query tile). 256 threads = 8 warps.
// Warp w owns query rows 8w..8w+7. Lane l owns key cols {l, l+32} in QK^T,
// and output cols 4l..4l+3 in PV.
// Shared: Qs[64][128] | Ks[128][65] (K transposed, padded) | Vs[64][128] | Ps[64][64]
// ---------------------------------------------------------------------------
#define KS_STRIDE 65
#define SMEM_FLOATS (64*128 + 128*KS_STRIDE + 64*128 + 64*64)

__global__ __launch_bounds__(256) void attn_kernel(float* __restrict__ out)
{
    extern __shared__ float sm[];
    float* Qs = sm;                        // 8192
    float* Ks = Qs + 64 * 128;             // 8320 (transposed [d][key], stride 65)
    float* Vs = Ks + 128 * KS_STRIDE;      // 8192
    float* Ps = Vs + 64 * 128;             // 4096

    const int t    = threadIdx.x;
    const int warp = t >> 5;
    const int lane = t & 31;
    const int b    = blockIdx.y;
    const int qt   = (int)gridDim.x - 1 - (int)blockIdx.x;   // heavy tiles first
    const int i0   = qt * 64;

    // ---- load Q tile (scaled by 1/sqrt(1024) = 1/32) ----
    const float* Qg = g_q + ((size_t)b * TT + i0) * HD;
    const float scale = 0.03125f;
    #pragma unroll
    for (int i = 0; i < 8; i++) {
        const int idx = t + i * 256;            // f4 index 0..2047
        const int r = idx >> 5;
        const int c = (idx & 31) << 2;
        float4 v = *reinterpret_cast<const float4*>(Qg + r * HD + c);
        v.x *= scale; v.y *= scale; v.z *= scale; v.w *= scale;
        *reinterpret_cast<float4*>(&Qs[r * HD + c]) = v;
    }

    float m[8], l[8], o[8][4];
    #pragma unroll
    for (int r = 0; r < 8; r++) {
        m[r] = -1e30f; l[r] = 0.f;
        o[r][0] = o[r][1] = o[r][2] = o[r][3] = 0.f;
    }

    for (int jt = 0; jt <= qt; jt++) {
        __syncthreads();   // protect Ks/Vs from previous iteration's readers

        // ---- load K (transposed into Ks[d][key]) and V tiles ----
        const float* Kg = g_k + ((size_t)b * TT + jt * 64) * HD;
        const float* Vg = g_v + ((size_t)b * TT + jt * 64) * HD;
        #pragma unroll
        for (int i = 0; i < 8; i++) {
            const int idx = t + i * 256;
            const int r = idx >> 5;             // key row 0..63
            const int c = (idx & 31) << 2;      // d 0..124
            float4 kv = *reinterpret_cast<const float4*>(Kg + r * HD + c);
            Ks[(c + 0) * KS_STRIDE + r] = kv.x;
            Ks[(c + 1) * KS_STRIDE + r] = kv.y;
            Ks[(c + 2) * KS_STRIDE + r] = kv.z;
            Ks[(c + 3) * KS_STRIDE + r] = kv.w;
            float4 vv = *reinterpret_cast<const float4*>(Vg + r * HD + c);
            *reinterpret_cast<float4*>(&Vs[r * HD + c]) = vv;
        }
        __syncthreads();

        // ---- S = Q K^T for 8 rows x 2 cols per thread ----
        float s0[8], s1[8];
        #pragma unroll
        for (int r = 0; r < 8; r++) { s0[r] = 0.f; s1[r] = 0.f; }

        #pragma unroll 2
        for (int d4 = 0; d4 < 32; d4++) {
            const int d = d4 << 2;
            const float k00 = Ks[(d + 0) * KS_STRIDE + lane];
            const float k01 = Ks[(d + 1) * KS_STRIDE + lane];
            const float k02 = Ks[(d + 2) * KS_STRIDE + lane];
            const float k03 = Ks[(d + 3) * KS_STRIDE + lane];
            const float k10 = Ks[(d + 0) * KS_STRIDE + lane + 32];
            const float k11 = Ks[(d + 1) * KS_STRIDE + lane + 32];
            const float k12 = Ks[(d + 2) * KS_STRIDE + lane + 32];
            const float k13 = Ks[(d + 3) * KS_STRIDE + lane + 32];
            #pragma unroll
            for (int r = 0; r < 8; r++) {
                float4 qv = *reinterpret_cast<const float4*>(&Qs[((warp << 3) + r) * HD + d]);
                s0[r] = fmaf(qv.x, k00, fmaf(qv.y, k01, fmaf(qv.z, k02, fmaf(qv.w, k03, s0[r]))));
                s1[r] = fmaf(qv.x, k10, fmaf(qv.y, k11, fmaf(qv.z, k12, fmaf(qv.w, k13, s1[r]))));
            }
        }

        // ---- online softmax ----
        const bool diag = (jt == qt);
        #pragma unroll
        for (int r = 0; r < 8; r++) {
            float a0 = s0[r], a1 = s1[r];
            if (diag) {
                const int rl = (warp << 3) + r;
                if (lane      > rl) a0 = -1e30f;
                if (lane + 32 > rl) a1 = -1e30f;
            }
            float tmax = fmaxf(a0, a1);
            #pragma unroll
            for (int off = 16; off; off >>= 1)
                tmax = fmaxf(tmax, __shfl_xor_sync(0xffffffffu, tmax, off));
            const float mnew = fmaxf(m[r], tmax);
            const float p0 = __expf(a0 - mnew);
            const float p1 = __expf(a1 - mnew);
            const float alpha = __expf(m[r] - mnew);
            float rsum = p0 + p1;
            #pragma unroll
            for (int off = 16; off; off >>= 1)
                rsum += __shfl_xor_sync(0xffffffffu, rsum, off);
            l[r] = l[r] * alpha + rsum;
            m[r] = mnew;
            o[r][0] *= alpha; o[r][1] *= alpha; o[r][2] *= alpha; o[r][3] *= alpha;
            Ps[((warp << 3) + r) * 64 + lane]      = p0;
            Ps[((warp << 3) + r) * 64 + lane + 32] = p1;
        }
        __syncwarp();   // Ps is warp-private: warp-level sync suffices

        // ---- O += P V : lane covers output cols 4l..4l+3 ----
        #pragma unroll 2
        for (int j = 0; j < 64; j++) {
            float4 vv = *reinterpret_cast<const float4*>(&Vs[j * HD + (lane << 2)]);
            #pragma unroll
            for (int r = 0; r < 8; r++) {
                const float p = Ps[((warp << 3) + r) * 64 + j];
                o[r][0] = fmaf(p, vv.x, o[r][0]);
                o[r][1] = fmaf(p, vv.y, o[r][1]);
                o[r][2] = fmaf(p, vv.z, o[r][2]);
                o[r][3] = fmaf(p, vv.w, o[r][3]);
            }
        }
    }

    // ---- epilogue: normalize + store ----
    #pragma unroll
    for (int r = 0; r < 8; r++) {
        const float inv = 1.0f / l[r];
        float4 v = make_float4(o[r][0] * inv, o[r][1] * inv, o[r][2] * inv, o[r][3] * inv);
        *reinterpret_cast<float4*>(
            out + ((size_t)b * TT + i0 + (warp << 3) + r) * HD + (lane << 2)) = v;
    }
}

// ---------------------------------------------------------------------------
extern "C" void kernel_launch(void* const* d_in, const int* in_sizes, int n_in,
                              void* d_out, int out_size)
{
    const float* X  = (const float*)d_in[0];   // index [8,2048,1024]
    const float* Wq = (const float*)d_in[1];   // [1024,128]
    const float* Wk = (const float*)d_in[2];
    const float* Wv = (const float*)d_in[3];
    float* out = (float*)d_out;                // [8,2048,128]

    (void)in_sizes; (void)n_in; (void)out_size;

    const int smem_bytes = SMEM_FLOATS * (int)sizeof(float);   // 115200 B
    cudaFuncSetAttribute(attn_kernel,
                         cudaFuncAttributeMaxDynamicSharedMemorySize, smem_bytes);

    qkv_gemm<<<dim3(BT / 64, 3), 256>>>(X, Wq, Wk, Wv);
    attn_kernel<<<dim3(TT / 64, BB), 256, smem_bytes>>>(out);
}

// round 3
// speedup vs baseline: 2.3082x; 2.3082x over previous
#include <cuda_runtime.h>
#include <cuda_bf16.h>
#include <cstdint>

#define BB   8
#define TT   2048
#define CIN  1024
#define HD   128
#define BT   (BB*TT)          // 16384 rows

typedef unsigned int u32;

// ---------------------------------------------------------------------------
// Device scratch (static globals: allocation-guard safe). bf16 hi/lo splits.
// ---------------------------------------------------------------------------
__device__ __align__(256) __nv_bfloat16 gQh[(size_t)BT * HD];
__device__ __align__(256) __nv_bfloat16 gQl[(size_t)BT * HD];
__device__ __align__(256) __nv_bfloat16 gKh[(size_t)BT * HD];
__device__ __align__(256) __nv_bfloat16 gKl[(size_t)BT * HD];
__device__ __align__(256) __nv_bfloat16 gVh[(size_t)BT * HD];
__device__ __align__(256) __nv_bfloat16 gVl[(size_t)BT * HD];
__device__ __align__(256) __nv_bfloat16 gWh[3][HD * CIN];   // W^T hi [o][n][k]
__device__ __align__(256) __nv_bfloat16 gWl[3][HD * CIN];   // W^T lo

// ---------------------------------------------------------------------------
// Helpers
// ---------------------------------------------------------------------------
__device__ __forceinline__ u32 pack_bf16(float x, float y) {
    __nv_bfloat162 h = __floats2bfloat162_rn(x, y);   // .x = low half
    return *reinterpret_cast<u32*>(&h);
}
__device__ __forceinline__ void split_pair(float x, float y, u32& hi, u32& lo) {
    float hx = __bfloat162float(__float2bfloat16(x));
    float hy = __bfloat162float(__float2bfloat16(y));
    hi = pack_bf16(hx, hy);
    lo = pack_bf16(x - hx, y - hy);
}
// D(16x8,f32) += A(16x16,bf16) * B(16x8,bf16)    row.col
__device__ __forceinline__ void mma_bf16(float* d, const u32* a, u32 b0, u32 b1) {
    asm volatile(
        "mma.sync.aligned.m16n8k16.row.col.f32.bf16.bf16.f32 "
        "{%0,%1,%2,%3}, {%4,%5,%6,%7}, {%8,%9}, {%0,%1,%2,%3};"
        : "+f"(d[0]), "+f"(d[1]), "+f"(d[2]), "+f"(d[3])
        : "r"(a[0]), "r"(a[1]), "r"(a[2]), "r"(a[3]), "r"(b0), "r"(b1));
}

// ---------------------------------------------------------------------------
// Kernel A: transpose + split weights: gW*[o][n*CIN+k] = split(W_o[k][n])
// ---------------------------------------------------------------------------
__global__ __launch_bounds__(256) void convert_w(const float* __restrict__ Wq,
                                                 const float* __restrict__ Wk,
                                                 const float* __restrict__ Wv)
{
    int idx = blockIdx.x * 256 + threadIdx.x;   // 0 .. 3*131072-1
    int o = idx >> 17;
    int r = idx & 0x1FFFF;
    int n = r & (HD - 1);
    int k = r >> 7;
    const float* W = (o == 0) ? Wq : (o == 1 ? Wk : Wv);
    float w  = W[k * HD + n];
    float hh = __bfloat162float(__float2bfloat16(w));
    gWh[o][n * CIN + k] = __float2bfloat16(hh);
    gWl[o][n * CIN + k] = __float2bfloat16(w - hh);
}

// ---------------------------------------------------------------------------
// Kernel B: QKV GEMM on HMMA. Out_o[16384,128] = X[16384,1024] @ W_o.
// CTA: BM=128, BN=128, BK=32. 8 warps in 4x2 grid: warp = 32 rows x 64 cols.
// hi/lo split: acc = Xh*Wh + Xh*Wl + Xl*Wh.  Epilogue -> bf16 hi/lo globals.
// ---------------------------------------------------------------------------
#define GS 56    // smem k-stride in bf16 (112B rows: 16B-aligned, conflict-free)
#define GEMM_SMEM (4 * 128 * GS * 2)

__global__ __launch_bounds__(256) void qkv_mma(const float* __restrict__ X)
{
    extern __shared__ __nv_bfloat16 smg[];
    __nv_bfloat16* Xh = smg;                 // [128][GS]
    __nv_bfloat16* Xl = Xh + 128 * GS;
    __nv_bfloat16* Wh = Xl + 128 * GS;       // [128 n][GS]
    __nv_bfloat16* Wl = Wh + 128 * GS;

    const int t    = threadIdx.x;
    const int lane = t & 31;
    const int wrp  = t >> 5;
    const int wm   = wrp >> 1;               // 0..3
    const int wn   = wrp & 1;                // 0..1
    const int g    = lane >> 2;              // 0..7
    const int qd   = (lane & 3) << 1;        // 0,2,4,6
    const int o    = blockIdx.y;
    const size_t m0 = (size_t)blockIdx.x * 128;

    const __nv_bfloat16* Wgh = gWh[o];
    const __nv_bfloat16* Wgl = gWl[o];

    float acc[2][8][4];
    #pragma unroll
    for (int mf = 0; mf < 2; mf++)
        #pragma unroll
        for (int nf = 0; nf < 8; nf++)
            #pragma unroll
            for (int e = 0; e < 4; e++) acc[mf][nf][e] = 0.f;

    for (int k0 = 0; k0 < CIN; k0 += 32) {
        __syncthreads();
        // X tile 128x32 fp32 -> split into Xh/Xl
        #pragma unroll
        for (int i = 0; i < 4; i++) {
            const int idx = t + i * 256;          // float4 idx 0..1023
            const int r   = idx >> 3;
            const int c4  = (idx & 7) << 2;
            float4 v = *reinterpret_cast<const float4*>(X + (m0 + r) * CIN + k0 + c4);
            u32 h0, l0, h1, l1;
            split_pair(v.x, v.y, h0, l0);
            split_pair(v.z, v.w, h1, l1);
            *reinterpret_cast<u32*>(&Xh[r * GS + c4])     = h0;
            *reinterpret_cast<u32*>(&Xh[r * GS + c4 + 2]) = h1;
            *reinterpret_cast<u32*>(&Xl[r * GS + c4])     = l0;
            *reinterpret_cast<u32*>(&Xl[r * GS + c4 + 2]) = l1;
        }
        // W tiles (already split/transposed): [128 n][32 k]
        #pragma unroll
        for (int i = 0; i < 2; i++) {
            const int idx = t + i * 256;          // uint4 idx 0..511
            const int n   = idx >> 2;
            const int c8  = (idx & 3) << 3;
            uint4 vh = *reinterpret_cast<const uint4*>(&Wgh[n * CIN + k0 + c8]);
            uint4 vl = *reinterpret_cast<const uint4*>(&Wgl[n * CIN + k0 + c8]);
            *reinterpret_cast<uint4*>(&Wh[n * GS + c8]) = vh;
            *reinterpret_cast<uint4*>(&Wl[n * GS + c8]) = vl;
        }
        __syncthreads();

        #pragma unroll
        for (int ks = 0; ks < 2; ks++) {
            const int kb = ks * 16 + qd;
            u32 ah[2][4], al[2][4];
            #pragma unroll
            for (int mf = 0; mf < 2; mf++) {
                const int r = wm * 32 + mf * 16 + g;
                ah[mf][0] = *reinterpret_cast<const u32*>(&Xh[r * GS + kb]);
                ah[mf][1] = *reinterpret_cast<const u32*>(&Xh[(r + 8) * GS + kb]);
                ah[mf][2] = *reinterpret_cast<const u32*>(&Xh[r * GS + kb + 8]);
                ah[mf][3] = *reinterpret_cast<const u32*>(&Xh[(r + 8) * GS + kb + 8]);
                al[mf][0] = *reinterpret_cast<const u32*>(&Xl[r * GS + kb]);
                al[mf][1] = *reinterpret_cast<const u32*>(&Xl[(r + 8) * GS + kb]);
                al[mf][2] = *reinterpret_cast<const u32*>(&Xl[r * GS + kb + 8]);
                al[mf][3] = *reinterpret_cast<const u32*>(&Xl[(r + 8) * GS + kb + 8]);
            }
            #pragma unroll
            for (int nf = 0; nf < 8; nf++) {
                const int n = wn * 64 + nf * 8 + g;
                u32 bh0 = *reinterpret_cast<const u32*>(&Wh[n * GS + kb]);
                u32 bh1 = *reinterpret_cast<const u32*>(&Wh[n * GS + kb + 8]);
                u32 bl0 = *reinterpret_cast<const u32*>(&Wl[n * GS + kb]);
                u32 bl1 = *reinterpret_cast<const u32*>(&Wl[n * GS + kb + 8]);
                #pragma unroll
                for (int mf = 0; mf < 2; mf++) {
                    mma_bf16(acc[mf][nf], ah[mf], bh0, bh1);
                    mma_bf16(acc[mf][nf], ah[mf], bl0, bl1);
                    mma_bf16(acc[mf][nf], al[mf], bh0, bh1);
                }
            }
        }
    }

    // Epilogue: scale Q by 1/sqrt(1024), split to bf16 hi/lo globals
    const float scale = (o == 0) ? 0.03125f : 1.0f;
    __nv_bfloat16* Gh = (o == 0) ? gQh : (o == 1 ? gKh : gVh);
    __nv_bfloat16* Gl = (o == 0) ? gQl : (o == 1 ? gKl : gVl);
    #pragma unroll
    for (int mf = 0; mf < 2; mf++) {
        const size_t r = m0 + wm * 32 + mf * 16 + g;
        #pragma unroll
        for (int nf = 0; nf < 8; nf++) {
            const int col = wn * 64 + nf * 8 + qd;
            u32 hi, lo;
            split_pair(acc[mf][nf][0] * scale, acc[mf][nf][1] * scale, hi, lo);
            *reinterpret_cast<u32*>(&Gh[r * HD + col]) = hi;
            *reinterpret_cast<u32*>(&Gl[r * HD + col]) = lo;
            split_pair(acc[mf][nf][2] * scale, acc[mf][nf][3] * scale, hi, lo);
            *reinterpret_cast<u32*>(&Gh[(r + 8) * HD + col]) = hi;
            *reinterpret_cast<u32*>(&Gl[(r + 8) * HD + col]) = lo;
        }
    }
}

// ---------------------------------------------------------------------------
// Kernel C: causal flash attention on HMMA.
// CTA: 64 q-rows, 4 warps (16 rows each), 64-key tiles, online softmax in
// registers. S D-fragments feed PV A-fragments directly (no smem round trip).
// ---------------------------------------------------------------------------
#define QS 136   // row stride (bf16) for Q/K tiles
#define VS 72    // row stride (bf16) for transposed V tiles
#define ATTN_SMEM ((4 * 64 * QS + 2 * 128 * VS) * 2)

__global__ __launch_bounds__(128) void attn_kernel(float* __restrict__ out)
{
    extern __shared__ __nv_bfloat16 sma[];
    __nv_bfloat16* Qh  = sma;                 // [64][QS]
    __nv_bfloat16* Ql  = Qh + 64 * QS;
    __nv_bfloat16* Kh  = Ql + 64 * QS;        // [64][QS]
    __nv_bfloat16* Kl  = Kh + 64 * QS;
    __nv_bfloat16* Vth = Kl + 64 * QS;        // [128 d][VS keys]
    __nv_bfloat16* Vtl = Vth + 128 * VS;

    const int t    = threadIdx.x;
    const int lane = t & 31;
    const int w    = t >> 5;                  // warp 0..3 -> rows w*16..+15
    const int g    = lane >> 2;               // 0..7
    const int qd   = (lane & 3) << 1;         // 0,2,4,6
    const int b    = blockIdx.y;
    const int qt   = (int)gridDim.x - 1 - (int)blockIdx.x;   // heavy first
    const int i0   = qt * 64;

    // ---- load Q tile (bf16 hi/lo, pre-scaled in GEMM) ----
    {
        const uint4* Qgh = reinterpret_cast<const uint4*>(gQh + ((size_t)b * TT + i0) * HD);
        const uint4* Qgl = reinterpret_cast<const uint4*>(gQl + ((size_t)b * TT + i0) * HD);
        #pragma unroll
        for (int i = 0; i < 8; i++) {
            const int idx = t + i * 128;      // uint4 idx 0..1023
            const int r   = idx >> 4;
            const int c8  = (idx & 15) << 3;
            *reinterpret_cast<uint4*>(&Qh[r * QS + c8]) = Qgh[idx];
            *reinterpret_cast<uint4*>(&Ql[r * QS + c8]) = Qgl[idx];
        }
    }

    float O[16][4];
    #pragma unroll
    for (int nf = 0; nf < 16; nf++)
        #pragma unroll
        for (int e = 0; e < 4; e++) O[nf][e] = 0.f;
    float mrow[2] = {-1e30f, -1e30f};
    float lrow[2] = {0.f, 0.f};

    for (int jt = 0; jt <= qt; jt++) {
        __syncthreads();    // smem reuse barrier (also covers Q on jt==0)

        // ---- load K tile (row-major copy) ----
        {
            const uint4* Kgh = reinterpret_cast<const uint4*>(gKh + ((size_t)b * TT + jt * 64) * HD);
            const uint4* Kgl = reinterpret_cast<const uint4*>(gKl + ((size_t)b * TT + jt * 64) * HD);
            #pragma unroll
            for (int i = 0; i < 8; i++) {
                const int idx = t + i * 128;
                const int r   = idx >> 4;
                const int c8  = (idx & 15) << 3;
                *reinterpret_cast<uint4*>(&Kh[r * QS + c8]) = Kgh[idx];
                *reinterpret_cast<uint4*>(&Kl[r * QS + c8]) = Kgl[idx];
            }
        }
        // ---- load V tile transposed: Vt[d][key] via byte_perm pair packing ----
        {
            const u32* Vg32h = reinterpret_cast<const u32*>(gVh + ((size_t)b * TT + jt * 64) * HD);
            const u32* Vg32l = reinterpret_cast<const u32*>(gVl + ((size_t)b * TT + jt * 64) * HD);
            #pragma unroll
            for (int i = 0; i < 16; i++) {
                const int idx = t + i * 128;           // dual-cell 0..2047
                const int dp  = idx & 63;              // d-pair 0..63
                const int rp  = idx >> 6;              // key-pair 0..31
                u32 a = Vg32h[(2 * rp) * 64 + dp];
                u32 c = Vg32h[(2 * rp + 1) * 64 + dp];
                *reinterpret_cast<u32*>(&Vth[(2 * dp) * VS + 2 * rp])     = __byte_perm(a, c, 0x5410);
                *reinterpret_cast<u32*>(&Vth[(2 * dp + 1) * VS + 2 * rp]) = __byte_perm(a, c, 0x7632);
                a = Vg32l[(2 * rp) * 64 + dp];
                c = Vg32l[(2 * rp + 1) * 64 + dp];
                *reinterpret_cast<u32*>(&Vtl[(2 * dp) * VS + 2 * rp])     = __byte_perm(a, c, 0x5410);
                *reinterpret_cast<u32*>(&Vtl[(2 * dp + 1) * VS + 2 * rp]) = __byte_perm(a, c, 0x7632);
            }
        }
        __syncthreads();

        // ---- S = Q K^T (hi*hi + hi*lo + lo*hi) ----
        float s[8][4];
        #pragma unroll
        for (int nf = 0; nf < 8; nf++)
            #pragma unroll
            for (int e = 0; e < 4; e++) s[nf][e] = 0.f;

        #pragma unroll
        for (int ks = 0; ks < 8; ks++) {
            const int kb = ks * 16 + qd;
            const int r  = w * 16 + g;
            u32 ah[4], al[4];
            ah[0] = *reinterpret_cast<const u32*>(&Qh[r * QS + kb]);
            ah[1] = *reinterpret_cast<const u32*>(&Qh[(r + 8) * QS + kb]);
            ah[2] = *reinterpret_cast<const u32*>(&Qh[r * QS + kb + 8]);
            ah[3] = *reinterpret_cast<const u32*>(&Qh[(r + 8) * QS + kb + 8]);
            al[0] = *reinterpret_cast<const u32*>(&Ql[r * QS + kb]);
            al[1] = *reinterpret_cast<const u32*>(&Ql[(r + 8) * QS + kb]);
            al[2] = *reinterpret_cast<const u32*>(&Ql[r * QS + kb + 8]);
            al[3] = *reinterpret_cast<const u32*>(&Ql[(r + 8) * QS + kb + 8]);
            #pragma unroll
            for (int nf = 0; nf < 8; nf++) {
                const int key = nf * 8 + g;
                u32 bh0 = *reinterpret_cast<const u32*>(&Kh[key * QS + kb]);
                u32 bh1 = *reinterpret_cast<const u32*>(&Kh[key * QS + kb + 8]);
                u32 bl0 = *reinterpret_cast<const u32*>(&Kl[key * QS + kb]);
                u32 bl1 = *reinterpret_cast<const u32*>(&Kl[key * QS + kb + 8]);
                mma_bf16(s[nf], ah, bh0, bh1);
                mma_bf16(s[nf], ah, bl0, bl1);
                mma_bf16(s[nf], al, bh0, bh1);
            }
        }

        // ---- causal mask on diagonal tile ----
        if (jt == qt) {
            #pragma unroll
            for (int nf = 0; nf < 8; nf++) {
                const int c0 = nf * 8 + qd;
                const int r0 = w * 16 + g;
                if (c0     > r0)     s[nf][0] = -1e30f;
                if (c0 + 1 > r0)     s[nf][1] = -1e30f;
                if (c0     > r0 + 8) s[nf][2] = -1e30f;
                if (c0 + 1 > r0 + 8) s[nf][3] = -1e30f;
            }
        }

        // ---- online softmax (rows g and g+8, reduce over quad) ----
        float mx0 = -1e30f, mx1 = -1e30f;
        #pragma unroll
        for (int nf = 0; nf < 8; nf++) {
            mx0 = fmaxf(mx0, fmaxf(s[nf][0], s[nf][1]));
            mx1 = fmaxf(mx1, fmaxf(s[nf][2], s[nf][3]));
        }
        mx0 = fmaxf(mx0, __shfl_xor_sync(0xffffffffu, mx0, 1));
        mx0 = fmaxf(mx0, __shfl_xor_sync(0xffffffffu, mx0, 2));
        mx1 = fmaxf(mx1, __shfl_xor_sync(0xffffffffu, mx1, 1));
        mx1 = fmaxf(mx1, __shfl_xor_sync(0xffffffffu, mx1, 2));
        const float mn0 = fmaxf(mrow[0], mx0);
        const float mn1 = fmaxf(mrow[1], mx1);
        const float a0  = __expf(mrow[0] - mn0);
        const float a1  = __expf(mrow[1] - mn1);
        mrow[0] = mn0; mrow[1] = mn1;

        float sum0 = 0.f, sum1 = 0.f;
        #pragma unroll
        for (int nf = 0; nf < 8; nf++) {
            s[nf][0] = __expf(s[nf][0] - mn0);
            s[nf][1] = __expf(s[nf][1] - mn0);
            s[nf][2] = __expf(s[nf][2] - mn1);
            s[nf][3] = __expf(s[nf][3] - mn1);
            sum0 += s[nf][0] + s[nf][1];
            sum1 += s[nf][2] + s[nf][3];
        }
        sum0 += __shfl_xor_sync(0xffffffffu, sum0, 1);
        sum0 += __shfl_xor_sync(0xffffffffu, sum0, 2);
        sum1 += __shfl_xor_sync(0xffffffffu, sum1, 1);
        sum1 += __shfl_xor_sync(0xffffffffu, sum1, 2);
        lrow[0] = lrow[0] * a0 + sum0;
        lrow[1] = lrow[1] * a1 + sum1;

        #pragma unroll
        for (int nf = 0; nf < 16; nf++) {
            O[nf][0] *= a0; O[nf][1] *= a0;
            O[nf][2] *= a1; O[nf][3] *= a1;
        }

        // ---- O += P V : P fragments built directly from S D-fragments ----
        #pragma unroll
        for (int ks = 0; ks < 4; ks++) {
            u32 ph[4], pl[4];
            split_pair(s[2 * ks][0],     s[2 * ks][1],     ph[0], pl[0]);
            split_pair(s[2 * ks][2],     s[2 * ks][3],     ph[1], pl[1]);
            split_pair(s[2 * ks + 1][0], s[2 * ks + 1][1], ph[2], pl[2]);
            split_pair(s[2 * ks + 1][2], s[2 * ks + 1][3], ph[3], pl[3]);
            const int kb = ks * 16 + qd;
            #pragma unroll
            for (int nf = 0; nf < 16; nf++) {
                const int d = nf * 8 + g;
                u32 bh0 = *reinterpret_cast<const u32*>(&Vth[d * VS + kb]);
                u32 bh1 = *reinterpret_cast<const u32*>(&Vth[d * VS + kb + 8]);
                u32 bl0 = *reinterpret_cast<const u32*>(&Vtl[d * VS + kb]);
                u32 bl1 = *reinterpret_cast<const u32*>(&Vtl[d * VS + kb + 8]);
                mma_bf16(O[nf], ph, bh0, bh1);
                mma_bf16(O[nf], ph, bl0, bl1);
                mma_bf16(O[nf], pl, bh0, bh1);
            }
        }
    }

    // ---- epilogue: normalize + store fp32 ----
    const float inv0 = 1.0f / lrow[0];
    const float inv1 = 1.0f / lrow[1];
    const size_t r0 = (size_t)b * TT + i0 + w * 16 + g;
    #pragma unroll
    for (int nf = 0; nf < 16; nf++) {
        const int col = nf * 8 + qd;
        float2 v0 = make_float2(O[nf][0] * inv0, O[nf][1] * inv0);
        float2 v1 = make_float2(O[nf][2] * inv1, O[nf][3] * inv1);
        *reinterpret_cast<float2*>(out + r0 * HD + col)       = v0;
        *reinterpret_cast<float2*>(out + (r0 + 8) * HD + col) = v1;
    }
}

// ---------------------------------------------------------------------------
extern "C" void kernel_launch(void* const* d_in, const int* in_sizes, int n_in,
                              void* d_out, int out_size)
{
    const float* X  = (const float*)d_in[0];   // [8,2048,1024]
    const float* Wq = (const float*)d_in[1];   // [1024,128]
    const float* Wk = (const float*)d_in[2];
    const float* Wv = (const float*)d_in[3];
    float* out = (float*)d_out;                // [8,2048,128]
    (void)in_sizes; (void)n_in; (void)out_size;

    cudaFuncSetAttribute(qkv_mma,
        cudaFuncAttributeMaxDynamicSharedMemorySize, GEMM_SMEM);
    cudaFuncSetAttribute(attn_kernel,
        cudaFuncAttributeMaxDynamicSharedMemorySize, ATTN_SMEM);

    convert_w<<<3 * HD * CIN / 256, 256>>>(Wq, Wk, Wv);
    qkv_mma<<<dim3(BT / 128, 3), 256, GEMM_SMEM>>>(X);
    attn_kernel<<<dim3(TT / 64, BB), 128, ATTN_SMEM>>>(out);
}

// round 4
// speedup vs baseline: 2.8354x; 1.2284x over previous
#include <cuda_runtime.h>
#include <cuda_bf16.h>
#include <cstdint>

#define BB   8
#define TT   2048
#define CIN  1024
#define HD   128
#define BT   (BB*TT)          // 16384 rows

typedef unsigned int u32;

// ---------------------------------------------------------------------------
// Device scratch (static globals: allocation-guard safe). bf16 hi/lo splits.
// ---------------------------------------------------------------------------
__device__ __align__(256) __nv_bfloat16 gQh[(size_t)BT * HD];
__device__ __align__(256) __nv_bfloat16 gQl[(size_t)BT * HD];
__device__ __align__(256) __nv_bfloat16 gKh[(size_t)BT * HD];
__device__ __align__(256) __nv_bfloat16 gKl[(size_t)BT * HD];
__device__ __align__(256) __nv_bfloat16 gVh[(size_t)BT * HD];
__device__ __align__(256) __nv_bfloat16 gVl[(size_t)BT * HD];
__device__ __align__(256) __nv_bfloat16 gWh[3][HD * CIN];   // W^T hi [o][n][k]
__device__ __align__(256) __nv_bfloat16 gWl[3][HD * CIN];   // W^T lo

// ---------------------------------------------------------------------------
// Helpers
// ---------------------------------------------------------------------------
__device__ __forceinline__ u32 pack_bf16(float x, float y) {
    __nv_bfloat162 h = __floats2bfloat162_rn(x, y);
    return *reinterpret_cast<u32*>(&h);
}
__device__ __forceinline__ void split_pair(float x, float y, u32& hi, u32& lo) {
    float hx = __bfloat162float(__float2bfloat16(x));
    float hy = __bfloat162float(__float2bfloat16(y));
    hi = pack_bf16(hx, hy);
    lo = pack_bf16(x - hx, y - hy);
}
__device__ __forceinline__ void mma_bf16(float* d, const u32* a, u32 b0, u32 b1) {
    asm volatile(
        "mma.sync.aligned.m16n8k16.row.col.f32.bf16.bf16.f32 "
        "{%0,%1,%2,%3}, {%4,%5,%6,%7}, {%8,%9}, {%0,%1,%2,%3};"
        : "+f"(d[0]), "+f"(d[1]), "+f"(d[2]), "+f"(d[3])
        : "r"(a[0]), "r"(a[1]), "r"(a[2]), "r"(a[3]), "r"(b0), "r"(b1));
}
__device__ __forceinline__ u32 smem_u32(const void* p) {
    u32 a;
    asm("{ .reg .u64 t; cvta.to.shared.u64 t, %1; cvt.u32.u64 %0, t; }"
        : "=r"(a) : "l"(p));
    return a;
}
__device__ __forceinline__ void ldsm4(u32 a, u32& r0, u32& r1, u32& r2, u32& r3) {
    asm volatile("ldmatrix.sync.aligned.m8n8.x4.shared.b16 {%0,%1,%2,%3}, [%4];"
                 : "=r"(r0), "=r"(r1), "=r"(r2), "=r"(r3) : "r"(a));
}
__device__ __forceinline__ void ldsm4t(u32 a, u32& r0, u32& r1, u32& r2, u32& r3) {
    asm volatile("ldmatrix.sync.aligned.m8n8.x4.trans.shared.b16 {%0,%1,%2,%3}, [%4];"
                 : "=r"(r0), "=r"(r1), "=r"(r2), "=r"(r3) : "r"(a));
}
#define CP16(dst, src) \
    asm volatile("cp.async.cg.shared.global [%0], [%1], 16;" \
                 :: "r"(dst), "l"(src) : "memory")
#define CP_COMMIT() asm volatile("cp.async.commit_group;" ::: "memory")
#define CP_WAIT(n)  asm volatile("cp.async.wait_group %0;" :: "n"(n) : "memory")

// ---------------------------------------------------------------------------
// Kernel A: transpose + split weights via smem tile (coalesced both sides).
// ---------------------------------------------------------------------------
__global__ void convert_w(const float* __restrict__ Wq,
                          const float* __restrict__ Wk,
                          const float* __restrict__ Wv)
{
    __shared__ float tile[32][33];
    const int o  = blockIdx.z;
    const float* W = (o == 0) ? Wq : (o == 1 ? Wk : Wv);
    const int n0 = blockIdx.x * 32;
    const int k0 = blockIdx.y * 32;
    const int tx = threadIdx.x, ty = threadIdx.y;

    #pragma unroll
    for (int i = ty; i < 32; i += 8)
        tile[i][tx] = W[(size_t)(k0 + i) * HD + n0 + tx];
    __syncthreads();
    #pragma unroll
    for (int i = ty; i < 32; i += 8) {
        float w  = tile[tx][i];                   // k = k0+tx, n = n0+i
        float hh = __bfloat162float(__float2bfloat16(w));
        gWh[o][(size_t)(n0 + i) * CIN + k0 + tx] = __float2bfloat16(hh);
        gWl[o][(size_t)(n0 + i) * CIN + k0 + tx] = __float2bfloat16(w - hh);
    }
}

// ---------------------------------------------------------------------------
// Kernel B: QKV GEMM. BM=128, BN=128, BK=32; 8 warps (4 wm x 2 wn).
// grid(3, 128): o fastest -> 3 CTAs with same m run together (X L2 reuse).
// ldmatrix fragments + register prefetch of next X/W tiles.
// ---------------------------------------------------------------------------
#define GS 40   // smem k-stride (halves): 80B rows, 16B aligned, LDSM-conflict-free
#define GEMM_SMEM (4 * 128 * GS * 2)

__global__ __launch_bounds__(256) void qkv_mma(const float* __restrict__ X)
{
    extern __shared__ __nv_bfloat16 smg[];
    __nv_bfloat16* Xh = smg;
    __nv_bfloat16* Xl = Xh + 128 * GS;
    __nv_bfloat16* Wh = Xl + 128 * GS;
    __nv_bfloat16* Wl = Wh + 128 * GS;
    const u32 Xh_b = smem_u32(Xh), Xl_b = smem_u32(Xl);
    const u32 Wh_b = smem_u32(Wh), Wl_b = smem_u32(Wl);

    const int t    = threadIdx.x;
    const int lane = t & 31;
    const int wrp  = t >> 5;
    const int wm   = wrp >> 1;
    const int wn   = wrp & 1;
    const int g    = lane >> 2;
    const int qd   = (lane & 3) << 1;
    const int j    = lane >> 3;
    const int lr   = lane & 7;
    const int o    = blockIdx.x;
    const size_t m0 = (size_t)blockIdx.y * 128;

    // ldmatrix byte offsets (stride 80B)
    u32 ga_off[2];
    #pragma unroll
    for (int mf = 0; mf < 2; mf++)
        ga_off[mf] = (wm * 32 + mf * 16 + ((j & 1) << 3) + lr) * 80 + ((j >> 1) << 4);
    const u32 gb_off = (wn * 64 + ((j >> 1) << 3) + lr) * 80 + ((j & 1) << 4);

    const __nv_bfloat16* Wgh = gWh[o];
    const __nv_bfloat16* Wgl = gWl[o];

    float acc[2][8][4];
    #pragma unroll
    for (int mf = 0; mf < 2; mf++)
        #pragma unroll
        for (int nf = 0; nf < 8; nf++)
            #pragma unroll
            for (int e = 0; e < 4; e++) acc[mf][nf][e] = 0.f;

    float4 xv[4];
    uint4  wvh[2], wvl[2];
    const int xr  = t >> 3;            // X row for loads
    const int xc  = (t & 7) << 2;      // X col (floats)
    const int wn_ = t >> 2;            // W row
    const int wc  = (t & 3) << 3;      // W col (halves)

    // prefetch iter 0
    #pragma unroll
    for (int i = 0; i < 4; i++)
        xv[i] = *reinterpret_cast<const float4*>(X + (m0 + xr + i * 32) * CIN + xc);
    #pragma unroll
    for (int i = 0; i < 2; i++) {
        wvh[i] = *reinterpret_cast<const uint4*>(&Wgh[(wn_ + i * 64) * CIN + wc]);
        wvl[i] = *reinterpret_cast<const uint4*>(&Wgl[(wn_ + i * 64) * CIN + wc]);
    }

    for (int it = 0; it < 32; it++) {
        __syncthreads();
        // store current tiles to smem (split X)
        #pragma unroll
        for (int i = 0; i < 4; i++) {
            u32 h0, l0, h1, l1;
            split_pair(xv[i].x, xv[i].y, h0, l0);
            split_pair(xv[i].z, xv[i].w, h1, l1);
            const int r = xr + i * 32;
            *reinterpret_cast<u32*>(&Xh[r * GS + xc])     = h0;
            *reinterpret_cast<u32*>(&Xh[r * GS + xc + 2]) = h1;
            *reinterpret_cast<u32*>(&Xl[r * GS + xc])     = l0;
            *reinterpret_cast<u32*>(&Xl[r * GS + xc + 2]) = l1;
        }
        #pragma unroll
        for (int i = 0; i < 2; i++) {
            *reinterpret_cast<uint4*>(&Wh[(wn_ + i * 64) * GS + wc]) = wvh[i];
            *reinterpret_cast<uint4*>(&Wl[(wn_ + i * 64) * GS + wc]) = wvl[i];
        }
        __syncthreads();

        if (it < 31) {
            const int k1 = (it + 1) * 32;
            #pragma unroll
            for (int i = 0; i < 4; i++)
                xv[i] = *reinterpret_cast<const float4*>(X + (m0 + xr + i * 32) * CIN + k1 + xc);
            #pragma unroll
            for (int i = 0; i < 2; i++) {
                wvh[i] = *reinterpret_cast<const uint4*>(&Wgh[(wn_ + i * 64) * CIN + k1 + wc]);
                wvl[i] = *reinterpret_cast<const uint4*>(&Wgl[(wn_ + i * 64) * CIN + k1 + wc]);
            }
        }

        #pragma unroll
        for (int ks = 0; ks < 2; ks++) {
            u32 ah[2][4], al[2][4];
            #pragma unroll
            for (int mf = 0; mf < 2; mf++) {
                ldsm4(Xh_b + ga_off[mf] + ks * 32, ah[mf][0], ah[mf][1], ah[mf][2], ah[mf][3]);
                ldsm4(Xl_b + ga_off[mf] + ks * 32, al[mf][0], al[mf][1], al[mf][2], al[mf][3]);
            }
            #pragma unroll
            for (int nf2 = 0; nf2 < 4; nf2++) {
                u32 bh0, bh1, bh2, bh3, bl0, bl1, bl2, bl3;
                ldsm4(Wh_b + gb_off + nf2 * (16 * 80) + ks * 32, bh0, bh1, bh2, bh3);
                ldsm4(Wl_b + gb_off + nf2 * (16 * 80) + ks * 32, bl0, bl1, bl2, bl3);
                #pragma unroll
                for (int mf = 0; mf < 2; mf++) {
                    mma_bf16(acc[mf][2 * nf2],     ah[mf], bh0, bh1);
                    mma_bf16(acc[mf][2 * nf2],     ah[mf], bl0, bl1);
                    mma_bf16(acc[mf][2 * nf2],     al[mf], bh0, bh1);
                    mma_bf16(acc[mf][2 * nf2 + 1], ah[mf], bh2, bh3);
                    mma_bf16(acc[mf][2 * nf2 + 1], ah[mf], bl2, bl3);
                    mma_bf16(acc[mf][2 * nf2 + 1], al[mf], bh2, bh3);
                }
            }
        }
    }

    // Epilogue: scale Q by 1/sqrt(1024), split to bf16 hi/lo globals
    const float scale = (o == 0) ? 0.03125f : 1.0f;
    __nv_bfloat16* Gh = (o == 0) ? gQh : (o == 1 ? gKh : gVh);
    __nv_bfloat16* Gl = (o == 0) ? gQl : (o == 1 ? gKl : gVl);
    #pragma unroll
    for (int mf = 0; mf < 2; mf++) {
        const size_t r = m0 + wm * 32 + mf * 16 + g;
        #pragma unroll
        for (int nf = 0; nf < 8; nf++) {
            const int col = wn * 64 + nf * 8 + qd;
            u32 hi, lo;
            split_pair(acc[mf][nf][0] * scale, acc[mf][nf][1] * scale, hi, lo);
            *reinterpret_cast<u32*>(&Gh[r * HD + col]) = hi;
            *reinterpret_cast<u32*>(&Gl[r * HD + col]) = lo;
            split_pair(acc[mf][nf][2] * scale, acc[mf][nf][3] * scale, hi, lo);
            *reinterpret_cast<u32*>(&Gh[(r + 8) * HD + col]) = hi;
            *reinterpret_cast<u32*>(&Gl[(r + 8) * HD + col]) = lo;
        }
    }
}

// ---------------------------------------------------------------------------
// Kernel C: causal flash attention.
// CTA: 64 q-rows, 4 warps. Q fragments held in registers for whole loop.
// K/V row-major in smem via cp.async (two commit groups -> V load overlaps S).
// K frags: ldmatrix.x4; V frags: ldmatrix.x4.trans (no explicit transpose).
// ---------------------------------------------------------------------------
#define AST 136                      // smem row stride in halves (272 B)
#define TILE_B (64 * AST * 2)        // one 64x128 bf16 tile: 17408 B
#define ATTN_SMEM (6 * TILE_B)       // Qh Ql Kh Kl Vh Vl = 104448 B

__device__ __forceinline__ void cp_tile64(u32 dst, const __nv_bfloat16* src, int t)
{
    #pragma unroll
    for (int i = 0; i < 8; i++) {
        const int c   = t + i * 128;
        const int row = c >> 4;
        const int col = c & 15;
        CP16(dst + row * 272 + col * 16, src + row * 128 + col * 8);
    }
}

__global__ __launch_bounds__(128) void attn_kernel(float* __restrict__ out)
{
    extern __shared__ __nv_bfloat16 sma[];
    const u32 base = smem_u32(sma);
    const u32 Qh_b = base,             Ql_b = base + TILE_B;
    const u32 Kh_b = base + 2*TILE_B,  Kl_b = base + 3*TILE_B;
    const u32 Vh_b = base + 4*TILE_B,  Vl_b = base + 5*TILE_B;

    const int t    = threadIdx.x;
    const int lane = t & 31;
    const int w    = t >> 5;
    const int g    = lane >> 2;
    const int qd   = (lane & 3) << 1;
    const int j    = lane >> 3;
    const int lr   = lane & 7;
    const int b    = blockIdx.y;
    const int qt   = (int)gridDim.x - 1 - (int)blockIdx.x;   // heavy first
    const int i0   = qt * 64;

    // ldmatrix byte offsets (stride 272B)
    const u32 a_off  = (w * 16 + ((j & 1) << 3) + lr) * 272 + ((j >> 1) << 4);
    const u32 kb_off = (((j >> 1) << 3) + lr) * 272 + ((j & 1) << 4);
    const u32 vb_off = (((j & 1) << 3) + lr) * 272 + ((j >> 1) << 4);

    // ---- Q tile -> smem (cp.async) -> register fragments ----
    {
        const __nv_bfloat16* Qgh = gQh + ((size_t)b * TT + i0) * HD;
        const __nv_bfloat16* Qgl = gQl + ((size_t)b * TT + i0) * HD;
        cp_tile64(Qh_b, Qgh, t);
        cp_tile64(Ql_b, Qgl, t);
        CP_COMMIT();
        CP_WAIT(0);
        __syncthreads();
    }
    u32 qh[8][4], ql[8][4];
    #pragma unroll
    for (int ks = 0; ks < 8; ks++) {
        ldsm4(Qh_b + a_off + ks * 32, qh[ks][0], qh[ks][1], qh[ks][2], qh[ks][3]);
        ldsm4(Ql_b + a_off + ks * 32, ql[ks][0], ql[ks][1], ql[ks][2], ql[ks][3]);
    }

    float O[16][4];
    #pragma unroll
    for (int nf = 0; nf < 16; nf++)
        #pragma unroll
        for (int e = 0; e < 4; e++) O[nf][e] = 0.f;
    float mrow[2] = {-1e30f, -1e30f};
    float lrow[2] = {0.f, 0.f};

    for (int jt = 0; jt <= qt; jt++) {
        __syncthreads();    // all warps done reading K/V of previous tile

        const __nv_bfloat16* Kgh = gKh + ((size_t)b * TT + jt * 64) * HD;
        const __nv_bfloat16* Kgl = gKl + ((size_t)b * TT + jt * 64) * HD;
        const __nv_bfloat16* Vgh = gVh + ((size_t)b * TT + jt * 64) * HD;
        const __nv_bfloat16* Vgl = gVl + ((size_t)b * TT + jt * 64) * HD;
        cp_tile64(Kh_b, Kgh, t);
        cp_tile64(Kl_b, Kgl, t);
        CP_COMMIT();
        cp_tile64(Vh_b, Vgh, t);
        cp_tile64(Vl_b, Vgl, t);
        CP_COMMIT();

        CP_WAIT(1);          // K arrived (V still in flight)
        __syncthreads();

        // ---- S = Q K^T (hi*hi + hi*lo + lo*hi) ----
        float s[8][4];
        #pragma unroll
        for (int nf = 0; nf < 8; nf++)
            #pragma unroll
            for (int e = 0; e < 4; e++) s[nf][e] = 0.f;

        #pragma unroll
        for (int ks = 0; ks < 8; ks++) {
            #pragma unroll
            for (int nf2 = 0; nf2 < 4; nf2++) {
                u32 bh0, bh1, bh2, bh3, bl0, bl1, bl2, bl3;
                ldsm4(Kh_b + kb_off + nf2 * (16 * 272) + ks * 32, bh0, bh1, bh2, bh3);
                ldsm4(Kl_b + kb_off + nf2 * (16 * 272) + ks * 32, bl0, bl1, bl2, bl3);
                mma_bf16(s[2 * nf2],     qh[ks], bh0, bh1);
                mma_bf16(s[2 * nf2],     qh[ks], bl0, bl1);
                mma_bf16(s[2 * nf2],     ql[ks], bh0, bh1);
                mma_bf16(s[2 * nf2 + 1], qh[ks], bh2, bh3);
                mma_bf16(s[2 * nf2 + 1], qh[ks], bl2, bl3);
                mma_bf16(s[2 * nf2 + 1], ql[ks], bh2, bh3);
            }
        }

        // ---- causal mask on diagonal tile ----
        if (jt == qt) {
            #pragma unroll
            for (int nf = 0; nf < 8; nf++) {
                const int c0 = nf * 8 + qd;
                const int r0 = w * 16 + g;
                if (c0     > r0)     s[nf][0] = -1e30f;
                if (c0 + 1 > r0)     s[nf][1] = -1e30f;
                if (c0     > r0 + 8) s[nf][2] = -1e30f;
                if (c0 + 1 > r0 + 8) s[nf][3] = -1e30f;
            }
        }

        // ---- online softmax ----
        float mx0 = -1e30f, mx1 = -1e30f;
        #pragma unroll
        for (int nf = 0; nf < 8; nf++) {
            mx0 = fmaxf(mx0, fmaxf(s[nf][0], s[nf][1]));
            mx1 = fmaxf(mx1, fmaxf(s[nf][2], s[nf][3]));
        }
        mx0 = fmaxf(mx0, __shfl_xor_sync(0xffffffffu, mx0, 1));
        mx0 = fmaxf(mx0, __shfl_xor_sync(0xffffffffu, mx0, 2));
        mx1 = fmaxf(mx1, __shfl_xor_sync(0xffffffffu, mx1, 1));
        mx1 = fmaxf(mx1, __shfl_xor_sync(0xffffffffu, mx1, 2));
        const float mn0 = fmaxf(mrow[0], mx0);
        const float mn1 = fmaxf(mrow[1], mx1);
        const float a0  = __expf(mrow[0] - mn0);
        const float a1  = __expf(mrow[1] - mn1);
        mrow[0] = mn0; mrow[1] = mn1;

        float sum0 = 0.f, sum1 = 0.f;
        #pragma unroll
        for (int nf = 0; nf < 8; nf++) {
            s[nf][0] = __expf(s[nf][0] - mn0);
            s[nf][1] = __expf(s[nf][1] - mn0);
            s[nf][2] = __expf(s[nf][2] - mn1);
            s[nf][3] = __expf(s[nf][3] - mn1);
            sum0 += s[nf][0] + s[nf][1];
            sum1 += s[nf][2] + s[nf][3];
        }
        sum0 += __shfl_xor_sync(0xffffffffu, sum0, 1);
        sum0 += __shfl_xor_sync(0xffffffffu, sum0, 2);
        sum1 += __shfl_xor_sync(0xffffffffu, sum1, 1);
        sum1 += __shfl_xor_sync(0xffffffffu, sum1, 2);
        lrow[0] = lrow[0] * a0 + sum0;
        lrow[1] = lrow[1] * a1 + sum1;

        #pragma unroll
        for (int nf = 0; nf < 16; nf++) {
            O[nf][0] *= a0; O[nf][1] *= a0;
            O[nf][2] *= a1; O[nf][3] *= a1;
        }

        CP_WAIT(0);          // V arrived
        __syncthreads();

        // ---- O += P V : V B-frags via ldmatrix.trans on row-major V ----
        #pragma unroll
        for (int ks = 0; ks < 4; ks++) {
            u32 ph[4], pl[4];
            split_pair(s[2 * ks][0],     s[2 * ks][1],     ph[0], pl[0]);
            split_pair(s[2 * ks][2],     s[2 * ks][3],     ph[1], pl[1]);
            split_pair(s[2 * ks + 1][0], s[2 * ks + 1][1], ph[2], pl[2]);
            split_pair(s[2 * ks + 1][2], s[2 * ks + 1][3], ph[3], pl[3]);
            #pragma unroll
            for (int nf2 = 0; nf2 < 8; nf2++) {
                u32 bh0, bh1, bh2, bh3, bl0, bl1, bl2, bl3;
                ldsm4t(Vh_b + vb_off + ks * (16 * 272) + nf2 * 32, bh0, bh1, bh2, bh3);
                ldsm4t(Vl_b + vb_off + ks * (16 * 272) + nf2 * 32, bl0, bl1, bl2, bl3);
                mma_bf16(O[2 * nf2],     ph, bh0, bh1);
                mma_bf16(O[2 * nf2],     ph, bl0, bl1);
                mma_bf16(O[2 * nf2],     pl, bh0, bh1);
                mma_bf16(O[2 * nf2 + 1], ph, bh2, bh3);
                mma_bf16(O[2 * nf2 + 1], ph, bl2, bl3);
                mma_bf16(O[2 * nf2 + 1], pl, bh2, bh3);
            }
        }
    }

    // ---- epilogue: normalize + store fp32 ----
    const float inv0 = 1.0f / lrow[0];
    const float inv1 = 1.0f / lrow[1];
    const size_t r0 = (size_t)b * TT + i0 + w * 16 + g;
    #pragma unroll
    for (int nf = 0; nf < 16; nf++) {
        const int col = nf * 8 + qd;
        float2 v0 = make_float2(O[nf][0] * inv0, O[nf][1] * inv0);
        float2 v1 = make_float2(O[nf][2] * inv1, O[nf][3] * inv1);
        *reinterpret_cast<float2*>(out + r0 * HD + col)       = v0;
        *reinterpret_cast<float2*>(out + (r0 + 8) * HD + col) = v1;
    }
}

// ---------------------------------------------------------------------------
extern "C" void kernel_launch(void* const* d_in, const int* in_sizes, int n_in,
                              void* d_out, int out_size)
{
    const float* X  = (const float*)d_in[0];   // [8,2048,1024]
    const float* Wq = (const float*)d_in[1];   // [1024,128]
    const float* Wk = (const float*)d_in[2];
    const float* Wv = (const float*)d_in[3];
    float* out = (float*)d_out;                // [8,2048,128]
    (void)in_sizes; (void)n_in; (void)out_size;

    cudaFuncSetAttribute(qkv_mma,
        cudaFuncAttributeMaxDynamicSharedMemorySize, GEMM_SMEM);
    cudaFuncSetAttribute(attn_kernel,
        cudaFuncAttributeMaxDynamicSharedMemorySize, ATTN_SMEM);

    convert_w<<<dim3(HD / 32, CIN / 32, 3), dim3(32, 8)>>>(Wq, Wk, Wv);
    qkv_mma<<<dim3(3, BT / 128), 256, GEMM_SMEM>>>(X);
    attn_kernel<<<dim3(TT / 64, BB), 128, ATTN_SMEM>>>(out);
}